// round 1
// baseline (speedup 1.0000x reference)
#include <cuda_runtime.h>
#include <math.h>

#define NMAX 100000
#define RMAX 3

// Scratch (device globals; no allocation allowed)
__device__ __align__(256) float g_z[(size_t)NMAX * 192];   // [N][3][64] accum -> z_r
__device__ __align__(256) float g_hsrc[(size_t)NMAX * 64]; // h_src for current relation
__device__ __align__(256) float g_el[NMAX];                // el for current relation
__device__ __align__(256) float g_er[RMAX * NMAX];         // er for all 3 relations
__device__ __align__(256) float g_den[RMAX * NMAX];        // softmax denominators
__device__ __align__(256) float g_wpart[4];                // semantic logit partial sums

// ---------- packed f32x2 helpers (sm_103a) ----------
__device__ __forceinline__ unsigned long long pack2(float a, float b) {
    unsigned long long r;
    asm("mov.b64 %0, {%1, %2};" : "=l"(r) : "f"(a), "f"(b));
    return r;
}
__device__ __forceinline__ void unpack2(unsigned long long v, float& a, float& b) {
    asm("mov.b64 {%0, %1}, %2;" : "=f"(a), "=f"(b) : "l"(v));
}
__device__ __forceinline__ void fma2(unsigned long long& d, unsigned long long a, unsigned long long b) {
    asm("fma.rn.f32x2 %0, %1, %2, %0;" : "+l"(d) : "l"(a), "l"(b));
}
__device__ __forceinline__ void red_add_v4(float* addr, float a, float b, float c, float d) {
    asm volatile("red.global.add.v4.f32 [%0], {%1, %2, %3, %4};"
                 :: "l"(addr), "f"(a), "f"(b), "f"(c), "f"(d) : "memory");
}

// ---------- zero scratch ----------
__global__ void k_zero(int nz4, int nden) {
    int i = blockIdx.x * blockDim.x + threadIdx.x;
    int stride = gridDim.x * blockDim.x;
    float4* z4 = (float4*)g_z;
    float4 zv = make_float4(0.f, 0.f, 0.f, 0.f);
    for (int j = i; j < nz4; j += stride) z4[j] = zv;
    for (int j = i; j < nden; j += stride) g_den[j] = 0.f;
    if (i < 4) g_wpart[i] = 0.f;
}

// ---------- GEMM: H = X@W + b ; ev[v] = H @ avec[v] ----------
// n_av==3 -> ev to g_er (h_dst path, H not stored); n_av==1 -> ev to g_el, H to g_hsrc.
__global__ __launch_bounds__(256) void k_gemm(
    const float* __restrict__ X, const float* __restrict__ W, const float* __restrict__ bias,
    const float* __restrict__ avecs, int n_av, int write_h, int M)
{
    __shared__ __align__(16) float Ws[128 * 64];
    __shared__ float bs[64];
    __shared__ float as[3 * 64];
    int tid = threadIdx.x;
    const float4* W4 = (const float4*)W;
    float4* Ws4 = (float4*)Ws;
    #pragma unroll
    for (int i = 0; i < 8; i++) Ws4[tid + 256 * i] = W4[tid + 256 * i];
    if (tid < 64) bs[tid] = bias[tid];
    if (tid < n_av * 64) as[tid] = avecs[tid];
    __syncthreads();

    int row = blockIdx.x * 256 + tid;
    if (row >= M) return;

    unsigned long long acc[32];
    #pragma unroll
    for (int j = 0; j < 32; j++) acc[j] = pack2(bs[2 * j], bs[2 * j + 1]);

    const float4* Xr = (const float4*)(X + (size_t)row * 128);
    const ulonglong2* Wp = (const ulonglong2*)Ws;

    #pragma unroll 4
    for (int k0 = 0; k0 < 32; k0++) {
        float4 xv = Xr[k0];
        #pragma unroll
        for (int kk = 0; kk < 4; kk++) {
            float xs = (kk == 0) ? xv.x : (kk == 1) ? xv.y : (kk == 2) ? xv.z : xv.w;
            unsigned long long xx = pack2(xs, xs);
            const ulonglong2* wr = Wp + (k0 * 4 + kk) * 16;
            #pragma unroll
            for (int j = 0; j < 16; j++) {
                ulonglong2 w = wr[j];
                fma2(acc[2 * j], w.x, xx);
                fma2(acc[2 * j + 1], w.y, xx);
            }
        }
    }

    float h[64];
    #pragma unroll
    for (int j = 0; j < 32; j++) unpack2(acc[j], h[2 * j], h[2 * j + 1]);

    if (write_h) {
        float4* o4 = (float4*)(g_hsrc + (size_t)row * 64);
        #pragma unroll
        for (int q = 0; q < 16; q++)
            o4[q] = make_float4(h[4 * q], h[4 * q + 1], h[4 * q + 2], h[4 * q + 3]);
    }
    float* evout = (n_av == 3) ? g_er : g_el;
    for (int v = 0; v < n_av; v++) {
        float e = 0.f;
        #pragma unroll
        for (int j = 0; j < 64; j++) e += h[j] * as[v * 64 + j];
        evout[(size_t)v * M + row] = e;
    }
}

// ---------- edge pass: num[dst] += p*h_src[src], den[dst] += p ----------
__global__ __launch_bounds__(256) void k_edge(
    const int* __restrict__ src, const int* __restrict__ dst,
    int r, int N, int E)
{
    int t = blockIdx.x * blockDim.x + threadIdx.x;
    int g = t >> 4;
    int lane = t & 15;
    int gsz = (gridDim.x * blockDim.x) >> 4;
    const float4* h4 = (const float4*)g_hsrc;
    const float* er = g_er + (size_t)r * N;
    float* den = g_den + (size_t)r * N;

    for (int e = g; e < E; e += gsz) {
        int s = __ldg(&src[e]);
        int d = __ldg(&dst[e]);
        float x = __ldg(&g_el[s]) + __ldg(&er[d]);
        float lr = x > 0.f ? x : 0.01f * x;
        float p = __expf(lr);
        float4 v = __ldg(&h4[(size_t)s * 16 + lane]);
        float* addr = g_z + (size_t)d * 192 + r * 64 + lane * 4;
        red_add_v4(addr, p * v.x, p * v.y, p * v.z, p * v.w);
        if (lane == 0) atomicAdd(&den[d], p);
    }
}

// ---------- finalize: z = elu(num/den), + fused semantic logit partials ----------
__global__ __launch_bounds__(256) void k_finalize(
    int r, const float* __restrict__ W1, const float* __restrict__ b1,
    const float* __restrict__ w2, int N)
{
    __shared__ __align__(16) float W1s[64 * 128];
    __shared__ float b1s[128], w2s[128];
    __shared__ float zbuf[8][64];
    __shared__ float wsum[8];
    int tid = threadIdx.x, wid = tid >> 5, lane = tid & 31;
    const float4* W14 = (const float4*)W1;
    float4* W1s4 = (float4*)W1s;
    #pragma unroll
    for (int i = 0; i < 8; i++) W1s4[tid + 256 * i] = W14[tid + 256 * i];
    if (tid < 128) { b1s[tid] = b1[tid]; w2s[tid] = w2[tid]; }
    __syncthreads();

    int row = blockIdx.x * 8 + wid;
    float t = 0.f;
    if (row < N) {
        float* zr = g_z + (size_t)row * 192 + r * 64;
        float den = g_den[(size_t)r * N + row];
        float dinv = den > 0.f ? 1.f / den : 0.f;   // zero-degree -> elu(0)=0
        float z0 = zr[lane] * dinv;
        float z1 = zr[32 + lane] * dinv;
        z0 = z0 > 0.f ? z0 : expm1f(z0);
        z1 = z1 > 0.f ? z1 : expm1f(z1);
        zr[lane] = z0;
        zr[32 + lane] = z1;
        zbuf[wid][lane] = z0;
        zbuf[wid][32 + lane] = z1;
        __syncwarp();

        unsigned long long h01 = pack2(b1s[4 * lane], b1s[4 * lane + 1]);
        unsigned long long h23 = pack2(b1s[4 * lane + 2], b1s[4 * lane + 3]);
        const ulonglong2* Wp = (const ulonglong2*)W1s;
        #pragma unroll 8
        for (int i = 0; i < 64; i++) {
            float zi = zbuf[wid][i];
            unsigned long long zz = pack2(zi, zi);
            ulonglong2 w = Wp[i * 32 + lane];
            fma2(h01, w.x, zz);
            fma2(h23, w.y, zz);
        }
        float h0, h1, h2, h3;
        unpack2(h01, h0, h1);
        unpack2(h23, h2, h3);
        h0 = tanhf(h0); h1 = tanhf(h1); h2 = tanhf(h2); h3 = tanhf(h3);
        t = h0 * w2s[4 * lane] + h1 * w2s[4 * lane + 1]
          + h2 * w2s[4 * lane + 2] + h3 * w2s[4 * lane + 3];
    }
    #pragma unroll
    for (int o = 16; o; o >>= 1) t += __shfl_xor_sync(0xffffffffu, t, o);
    if (lane == 0) wsum[wid] = t;
    __syncthreads();
    if (wid == 0 && lane < 8) {
        float s = wsum[lane];
        #pragma unroll
        for (int o = 4; o; o >>= 1) s += __shfl_xor_sync(0xffu, s, o);
        if (lane == 0) atomicAdd(&g_wpart[r], s);
    }
}

// ---------- semantic softmax + mix ----------
__global__ void k_mix(float* __restrict__ out, int N, float invN) {
    float w0 = g_wpart[0] * invN, w1 = g_wpart[1] * invN, w2v = g_wpart[2] * invN;
    float m = fmaxf(w0, fmaxf(w1, w2v));
    float e0 = __expf(w0 - m), e1 = __expf(w1 - m), e2 = __expf(w2v - m);
    float si = 1.f / (e0 + e1 + e2);
    float a0 = e0 * si, a1 = e1 * si, a2 = e2 * si;

    const float4* z4 = (const float4*)g_z;
    float4* o4 = (float4*)out;
    int total = N * 16;
    int i = blockIdx.x * blockDim.x + threadIdx.x;
    int stride = gridDim.x * blockDim.x;
    for (int idx = i; idx < total; idx += stride) {
        int n = idx >> 4, q = idx & 15;
        float4 v0 = z4[(size_t)n * 48 + q];
        float4 v1 = z4[(size_t)n * 48 + 16 + q];
        float4 v2 = z4[(size_t)n * 48 + 32 + q];
        float4 o;
        o.x = a0 * v0.x + a1 * v1.x + a2 * v2.x;
        o.y = a0 * v0.y + a1 * v1.y + a2 * v2.y;
        o.z = a0 * v0.z + a1 * v1.z + a2 * v2.z;
        o.w = a0 * v0.w + a1 * v1.w + a2 * v2.w;
        o4[idx] = o;
    }
}

extern "C" void kernel_launch(void* const* d_in, const int* in_sizes, int n_in,
                              void* d_out, int out_size) {
    const float* dst_feat = (const float*)d_in[0];
    const float* neigh    = (const float*)d_in[1];
    const float* Wt       = (const float*)d_in[2];
    const float* bt       = (const float*)d_in[3];
    const float* attn_l   = (const float*)d_in[4];
    const float* attn_r   = (const float*)d_in[5];
    const float* W1       = (const float*)d_in[6];
    const float* b1       = (const float*)d_in[7];
    const float* w2       = (const float*)d_in[8];
    const int*   src      = (const int*)d_in[9];
    const int*   dst      = (const int*)d_in[10];

    int N  = in_sizes[0] / 128;          // 100000
    int Ns = in_sizes[1] / (3 * 128);    // 100000
    int E  = in_sizes[9] / 3;            // 1000000
    (void)n_in; (void)out_size;

    k_zero<<<2048, 256>>>(N * 48, 3 * N);

    // h_dst GEMM -> er for all 3 relations (H itself not needed)
    k_gemm<<<(N + 255) / 256, 256>>>(dst_feat, Wt, bt, attn_r, 3, 0, N);

    for (int r = 0; r < 3; r++) {
        const float* X  = neigh + (size_t)r * Ns * 128;
        const float* Wr = Wt + (size_t)(r + 1) * 128 * 64;
        const float* br = bt + (size_t)(r + 1) * 64;
        k_gemm<<<(Ns + 255) / 256, 256>>>(X, Wr, br, attn_l + (size_t)r * 64, 1, 1, Ns);
        k_edge<<<1184, 256>>>(src + (size_t)r * E, dst + (size_t)r * E, r, N, E);
        k_finalize<<<(N + 7) / 8, 256>>>(r, W1, b1, w2, N);
    }

    k_mix<<<1024, 256>>>((float*)d_out, N, 1.0f / (float)N);
}